// round 13
// baseline (speedup 1.0000x reference)
#include <cuda_runtime.h>
#include <cuda_fp16.h>
#include <cstdint>

// MeanAggregator: out[b, :] = mean_k features[neigh_idx[b, k], :]
// B=16384, K=15, U=19997, D=256 (idx int32 on device)
//
//  1) convert: fp32 -> fp16 shadow, persistent 592x256 grid-stride
//     (~4.2 iters/thread -> deeper load pipelining), plain loads so the
//     fp32 table stays L2-resident across graph replays.
//  2) gather (R11/R12, measured best 13.6us): grid 2048x256, 1 warp = 1 row,
//     indices pre-scaled to uint4-row offsets in smem, 15 back-to-back
//     LDG.128 per lane, fp32 accumulate, fp32 out.

#define K_NEIGH 15
#define D_DIM 256
#define U_ROWS 19997
#define WARPS_PER_BLOCK 8
#define CONV_BLOCKS (148 * 4)
#define NTHREADS 256

__device__ __half g_feat_h[(size_t)U_ROWS * D_DIM];

// ---- Pass 1: fp32 -> fp16 (8 floats in / 8 halves out per iter) ----
__global__ __launch_bounds__(NTHREADS)
void convert_kernel(const float* __restrict__ f, int n8)
{
    const float4* src = reinterpret_cast<const float4*>(f);
    uint4*        dst = reinterpret_cast<uint4*>(g_feat_h);
    const int stride = gridDim.x * NTHREADS;

    for (int i = blockIdx.x * NTHREADS + threadIdx.x; i < n8; i += stride) {
        float4 a = src[i * 2 + 0];
        float4 b = src[i * 2 + 1];
        uint4 d;
        __half2* h = reinterpret_cast<__half2*>(&d);
        h[0] = __floats2half2_rn(a.x, a.y);
        h[1] = __floats2half2_rn(a.z, a.w);
        h[2] = __floats2half2_rn(b.x, b.y);
        h[3] = __floats2half2_rn(b.z, b.w);
        dst[i] = d;
    }
}

// ---- Pass 2: gather + mean. One warp per output row. ----
__global__ __launch_bounds__(NTHREADS)
void gather_kernel(const int* __restrict__ neigh_idx,
                   float* __restrict__ out,
                   int B)
{
    __shared__ int soff[WARPS_PER_BLOCK][K_NEIGH + 1];   // uint4-row offsets

    const int tid  = threadIdx.x;
    const int warp = tid >> 5;
    const int lane = tid & 31;
    const int row0 = blockIdx.x * WARPS_PER_BLOCK;

    if (tid < WARPS_PER_BLOCK * K_NEIGH) {
        const int r = tid / K_NEIGH, c = tid % K_NEIGH;
        if (row0 + r < B)
            soff[r][c] = neigh_idx[(row0 + r) * K_NEIGH + c] * (D_DIM / 8);
    }
    __syncthreads();

    const int row = row0 + warp;
    if (row >= B) return;

    const uint4* __restrict__ f = reinterpret_cast<const uint4*>(g_feat_h);

    float acc[8] = {0.f, 0.f, 0.f, 0.f, 0.f, 0.f, 0.f, 0.f};

    #pragma unroll
    for (int k = 0; k < K_NEIGH; ++k) {
        const uint4 v = f[soff[warp][k] + lane];         // 32 uint4 per row
        const __half2* h = reinterpret_cast<const __half2*>(&v);
        #pragma unroll
        for (int j = 0; j < 4; ++j) {
            float2 p = __half22float2(h[j]);
            acc[j * 2]     += p.x;
            acc[j * 2 + 1] += p.y;
        }
    }

    const float inv = 1.0f / (float)K_NEIGH;
    float4 o0 = make_float4(acc[0]*inv, acc[1]*inv, acc[2]*inv, acc[3]*inv);
    float4 o1 = make_float4(acc[4]*inv, acc[5]*inv, acc[6]*inv, acc[7]*inv);

    float4* __restrict__ op = reinterpret_cast<float4*>(out + (size_t)row * D_DIM + lane * 8);
    op[0] = o0;
    op[1] = o1;
}

extern "C" void kernel_launch(void* const* d_in, const int* in_sizes, int n_in,
                              void* d_out, int out_size)
{
    int idx_slot = 0, feat_slot = 1;
    if (n_in >= 2 && in_sizes[0] > in_sizes[1]) { idx_slot = 1; feat_slot = 0; }

    const int*   neigh_idx = (const int*)d_in[idx_slot];     // [B, K] int32
    const float* features  = (const float*)d_in[feat_slot];  // [U, D] fp32
    float*       out       = (float*)d_out;                  // [B, D] fp32

    const int B  = in_sizes[idx_slot] / K_NEIGH;
    const int n8 = in_sizes[feat_slot] / 8;                  // 639,904

    convert_kernel<<<CONV_BLOCKS, NTHREADS>>>(features, n8);

    dim3 block(NTHREADS);
    dim3 grid((B + WARPS_PER_BLOCK - 1) / WARPS_PER_BLOCK);
    gather_kernel<<<grid, block>>>(neigh_idx, out, B);
}

// round 14
// speedup vs baseline: 1.3222x; 1.3222x over previous
#include <cuda_runtime.h>
#include <cuda_fp16.h>
#include <cstdint>

// MeanAggregator: out[b, :] = mean_k features[neigh_idx[b, k], :]
// B=16384, K=15, U=19997, D=256 (idx int32 on device)
//
// Final configuration (reproduced best, 16.83us wall):
//  1) convert: fp32 -> fp16 shadow, grid-stride 1184x256, plain loads
//     (fp32 table stays L2-resident across graph replays)  [~2.7us]
//  2) gather: grid 2048x256, 1 warp = 1 row, indices pre-scaled to
//     uint4-row offsets in smem, 15 back-to-back LDG.128 per lane,
//     fp32 accumulate, fp32 out  [~13.6-13.9us, ~85-88% of LTS cap]

#define K_NEIGH 15
#define D_DIM 256
#define U_ROWS 19997
#define WARPS_PER_BLOCK 8
#define CONV_BLOCKS (148 * 8)
#define NTHREADS 256

__device__ __half g_feat_h[(size_t)U_ROWS * D_DIM];

// ---- Pass 1: fp32 -> fp16 (8 floats in / 8 halves out per iter) ----
__global__ __launch_bounds__(NTHREADS)
void convert_kernel(const float* __restrict__ f, int n8)
{
    const float4* src = reinterpret_cast<const float4*>(f);
    uint4*        dst = reinterpret_cast<uint4*>(g_feat_h);
    const int stride = gridDim.x * NTHREADS;

    for (int i = blockIdx.x * NTHREADS + threadIdx.x; i < n8; i += stride) {
        float4 a = src[i * 2 + 0];
        float4 b = src[i * 2 + 1];
        uint4 d;
        __half2* h = reinterpret_cast<__half2*>(&d);
        h[0] = __floats2half2_rn(a.x, a.y);
        h[1] = __floats2half2_rn(a.z, a.w);
        h[2] = __floats2half2_rn(b.x, b.y);
        h[3] = __floats2half2_rn(b.z, b.w);
        dst[i] = d;
    }
}

// ---- Pass 2: gather + mean. One warp per output row. ----
__global__ __launch_bounds__(NTHREADS)
void gather_kernel(const int* __restrict__ neigh_idx,
                   float* __restrict__ out,
                   int B)
{
    __shared__ int soff[WARPS_PER_BLOCK][K_NEIGH + 1];   // uint4-row offsets

    const int tid  = threadIdx.x;
    const int warp = tid >> 5;
    const int lane = tid & 31;
    const int row0 = blockIdx.x * WARPS_PER_BLOCK;

    if (tid < WARPS_PER_BLOCK * K_NEIGH) {
        const int r = tid / K_NEIGH, c = tid % K_NEIGH;
        if (row0 + r < B)
            soff[r][c] = neigh_idx[(row0 + r) * K_NEIGH + c] * (D_DIM / 8);
    }
    __syncthreads();

    const int row = row0 + warp;
    if (row >= B) return;

    const uint4* __restrict__ f = reinterpret_cast<const uint4*>(g_feat_h);

    float acc[8] = {0.f, 0.f, 0.f, 0.f, 0.f, 0.f, 0.f, 0.f};

    #pragma unroll
    for (int k = 0; k < K_NEIGH; ++k) {
        const uint4 v = f[soff[warp][k] + lane];         // 32 uint4 per row
        const __half2* h = reinterpret_cast<const __half2*>(&v);
        #pragma unroll
        for (int j = 0; j < 4; ++j) {
            float2 p = __half22float2(h[j]);
            acc[j * 2]     += p.x;
            acc[j * 2 + 1] += p.y;
        }
    }

    const float inv = 1.0f / (float)K_NEIGH;
    float4 o0 = make_float4(acc[0]*inv, acc[1]*inv, acc[2]*inv, acc[3]*inv);
    float4 o1 = make_float4(acc[4]*inv, acc[5]*inv, acc[6]*inv, acc[7]*inv);

    float4* __restrict__ op = reinterpret_cast<float4*>(out + (size_t)row * D_DIM + lane * 8);
    op[0] = o0;
    op[1] = o1;
}

extern "C" void kernel_launch(void* const* d_in, const int* in_sizes, int n_in,
                              void* d_out, int out_size)
{
    int idx_slot = 0, feat_slot = 1;
    if (n_in >= 2 && in_sizes[0] > in_sizes[1]) { idx_slot = 1; feat_slot = 0; }

    const int*   neigh_idx = (const int*)d_in[idx_slot];     // [B, K] int32
    const float* features  = (const float*)d_in[feat_slot];  // [U, D] fp32
    float*       out       = (float*)d_out;                  // [B, D] fp32

    const int B  = in_sizes[idx_slot] / K_NEIGH;
    const int n8 = in_sizes[feat_slot] / 8;                  // 639,904

    convert_kernel<<<CONV_BLOCKS, NTHREADS>>>(features, n8);

    dim3 block(NTHREADS);
    dim3 grid((B + WARPS_PER_BLOCK - 1) / WARPS_PER_BLOCK);
    gather_kernel<<<grid, block>>>(neigh_idx, out, B);
}

// round 15
// speedup vs baseline: 1.3585x; 1.0274x over previous
#include <cuda_runtime.h>
#include <cuda_fp16.h>
#include <cstdint>

// MeanAggregator: out[b, :] = mean_k features[neigh_idx[b, k], :]
// B=16384, K=15, U=19997, D=256 (idx int32 on device)
//
// FINAL configuration (best reproduced: 16.83us wall; run-to-run DVFS
// variance puts identical code in a 16.8-19.2us band):
//  1) convert: fp32 -> fp16 shadow table, grid-stride 1184x256, plain
//     loads (fp32 table stays L2-resident across graph replays) [~2.7us]
//  2) gather: grid 2048x256, 1 warp = 1 row, indices pre-scaled to
//     uint4-row offsets in smem, 15 back-to-back LDG.128 per lane,
//     fp32 accumulate, fp32 out [13.6-14.6us, ~85-90% of the LTS
//     random-512B-row cap; DRAM ~10% (compulsory only)]
//
// Rationale log: fp16 shadow halves the dominant gather traffic
// (251MB -> 126MB, rel_err 2.1e-4 << 1e-3). fp8 would breach 1e-3.
// cp.async, 2-rows/warp, shfl, fusion, persistence all measured <= this.

#define K_NEIGH 15
#define D_DIM 256
#define U_ROWS 19997
#define WARPS_PER_BLOCK 8
#define CONV_BLOCKS (148 * 8)
#define NTHREADS 256

__device__ __half g_feat_h[(size_t)U_ROWS * D_DIM];

// ---- Pass 1: fp32 -> fp16 (8 floats in / 8 halves out per iter) ----
__global__ __launch_bounds__(NTHREADS)
void convert_kernel(const float* __restrict__ f, int n8)
{
    const float4* src = reinterpret_cast<const float4*>(f);
    uint4*        dst = reinterpret_cast<uint4*>(g_feat_h);
    const int stride = gridDim.x * NTHREADS;

    for (int i = blockIdx.x * NTHREADS + threadIdx.x; i < n8; i += stride) {
        float4 a = src[i * 2 + 0];
        float4 b = src[i * 2 + 1];
        uint4 d;
        __half2* h = reinterpret_cast<__half2*>(&d);
        h[0] = __floats2half2_rn(a.x, a.y);
        h[1] = __floats2half2_rn(a.z, a.w);
        h[2] = __floats2half2_rn(b.x, b.y);
        h[3] = __floats2half2_rn(b.z, b.w);
        dst[i] = d;
    }
}

// ---- Pass 2: gather + mean. One warp per output row. ----
__global__ __launch_bounds__(NTHREADS)
void gather_kernel(const int* __restrict__ neigh_idx,
                   float* __restrict__ out,
                   int B)
{
    __shared__ int soff[WARPS_PER_BLOCK][K_NEIGH + 1];   // uint4-row offsets

    const int tid  = threadIdx.x;
    const int warp = tid >> 5;
    const int lane = tid & 31;
    const int row0 = blockIdx.x * WARPS_PER_BLOCK;

    if (tid < WARPS_PER_BLOCK * K_NEIGH) {
        const int r = tid / K_NEIGH, c = tid % K_NEIGH;
        if (row0 + r < B)
            soff[r][c] = neigh_idx[(row0 + r) * K_NEIGH + c] * (D_DIM / 8);
    }
    __syncthreads();

    const int row = row0 + warp;
    if (row >= B) return;

    const uint4* __restrict__ f = reinterpret_cast<const uint4*>(g_feat_h);

    float acc[8] = {0.f, 0.f, 0.f, 0.f, 0.f, 0.f, 0.f, 0.f};

    #pragma unroll
    for (int k = 0; k < K_NEIGH; ++k) {
        const uint4 v = f[soff[warp][k] + lane];         // 32 uint4 per row
        const __half2* h = reinterpret_cast<const __half2*>(&v);
        #pragma unroll
        for (int j = 0; j < 4; ++j) {
            float2 p = __half22float2(h[j]);
            acc[j * 2]     += p.x;
            acc[j * 2 + 1] += p.y;
        }
    }

    const float inv = 1.0f / (float)K_NEIGH;
    float4 o0 = make_float4(acc[0]*inv, acc[1]*inv, acc[2]*inv, acc[3]*inv);
    float4 o1 = make_float4(acc[4]*inv, acc[5]*inv, acc[6]*inv, acc[7]*inv);

    float4* __restrict__ op = reinterpret_cast<float4*>(out + (size_t)row * D_DIM + lane * 8);
    op[0] = o0;
    op[1] = o1;
}

extern "C" void kernel_launch(void* const* d_in, const int* in_sizes, int n_in,
                              void* d_out, int out_size)
{
    int idx_slot = 0, feat_slot = 1;
    if (n_in >= 2 && in_sizes[0] > in_sizes[1]) { idx_slot = 1; feat_slot = 0; }

    const int*   neigh_idx = (const int*)d_in[idx_slot];     // [B, K] int32
    const float* features  = (const float*)d_in[feat_slot];  // [U, D] fp32
    float*       out       = (float*)d_out;                  // [B, D] fp32

    const int B  = in_sizes[idx_slot] / K_NEIGH;
    const int n8 = in_sizes[feat_slot] / 8;                  // 639,904

    convert_kernel<<<CONV_BLOCKS, NTHREADS>>>(features, n8);

    dim3 block(NTHREADS);
    dim3 grid((B + WARPS_PER_BLOCK - 1) / WARPS_PER_BLOCK);
    gather_kernel<<<grid, block>>>(neigh_idx, out, B);
}

// round 16
// speedup vs baseline: 1.5028x; 1.1063x over previous
#include <cuda_runtime.h>
#include <cuda_fp16.h>
#include <cstdint>

// MeanAggregator: out[b, :] = mean_k features[neigh_idx[b, k], :]
// B=16384, K=15, U=19997, D=256 (idx int32 on device)
//
// FINAL configuration (converged). Best measured wall 16.83us; identical
// source measures 16.8-19.2us across runs (NAT-clock DVFS band, +-8%).
//  1) convert: fp32 -> fp16 shadow table, grid-stride 1184x256, plain
//     loads (fp32 table stays L2-resident across graph replays) [~2.7us]
//  2) gather: grid 2048x256, 1 warp = 1 row, indices pre-scaled to
//     uint4-row offsets in smem, 15 back-to-back LDG.128 per lane,
//     fp32 accumulate, fp32 out [13.6-14.6us, ~88% of the LTS
//     random-512B-row service cap; DRAM ~10% = compulsory floor]
//
// Ledger: fp16 shadow halves dominant gather traffic (rel_err 2.1e-4).
// fp8 would breach 1e-3. cp.async, 2-rows/warp, shfl indices, grid-barrier
// fusion, persistent grids, convert reshapes: all measured <= this config.

#define K_NEIGH 15
#define D_DIM 256
#define U_ROWS 19997
#define WARPS_PER_BLOCK 8
#define CONV_BLOCKS (148 * 8)
#define NTHREADS 256

__device__ __half g_feat_h[(size_t)U_ROWS * D_DIM];

// ---- Pass 1: fp32 -> fp16 (8 floats in / 8 halves out per iter) ----
__global__ __launch_bounds__(NTHREADS)
void convert_kernel(const float* __restrict__ f, int n8)
{
    const float4* src = reinterpret_cast<const float4*>(f);
    uint4*        dst = reinterpret_cast<uint4*>(g_feat_h);
    const int stride = gridDim.x * NTHREADS;

    for (int i = blockIdx.x * NTHREADS + threadIdx.x; i < n8; i += stride) {
        float4 a = src[i * 2 + 0];
        float4 b = src[i * 2 + 1];
        uint4 d;
        __half2* h = reinterpret_cast<__half2*>(&d);
        h[0] = __floats2half2_rn(a.x, a.y);
        h[1] = __floats2half2_rn(a.z, a.w);
        h[2] = __floats2half2_rn(b.x, b.y);
        h[3] = __floats2half2_rn(b.z, b.w);
        dst[i] = d;
    }
}

// ---- Pass 2: gather + mean. One warp per output row. ----
__global__ __launch_bounds__(NTHREADS)
void gather_kernel(const int* __restrict__ neigh_idx,
                   float* __restrict__ out,
                   int B)
{
    __shared__ int soff[WARPS_PER_BLOCK][K_NEIGH + 1];   // uint4-row offsets

    const int tid  = threadIdx.x;
    const int warp = tid >> 5;
    const int lane = tid & 31;
    const int row0 = blockIdx.x * WARPS_PER_BLOCK;

    if (tid < WARPS_PER_BLOCK * K_NEIGH) {
        const int r = tid / K_NEIGH, c = tid % K_NEIGH;
        if (row0 + r < B)
            soff[r][c] = neigh_idx[(row0 + r) * K_NEIGH + c] * (D_DIM / 8);
    }
    __syncthreads();

    const int row = row0 + warp;
    if (row >= B) return;

    const uint4* __restrict__ f = reinterpret_cast<const uint4*>(g_feat_h);

    float acc[8] = {0.f, 0.f, 0.f, 0.f, 0.f, 0.f, 0.f, 0.f};

    #pragma unroll
    for (int k = 0; k < K_NEIGH; ++k) {
        const uint4 v = f[soff[warp][k] + lane];         // 32 uint4 per row
        const __half2* h = reinterpret_cast<const __half2*>(&v);
        #pragma unroll
        for (int j = 0; j < 4; ++j) {
            float2 p = __half22float2(h[j]);
            acc[j * 2]     += p.x;
            acc[j * 2 + 1] += p.y;
        }
    }

    const float inv = 1.0f / (float)K_NEIGH;
    float4 o0 = make_float4(acc[0]*inv, acc[1]*inv, acc[2]*inv, acc[3]*inv);
    float4 o1 = make_float4(acc[4]*inv, acc[5]*inv, acc[6]*inv, acc[7]*inv);

    float4* __restrict__ op = reinterpret_cast<float4*>(out + (size_t)row * D_DIM + lane * 8);
    op[0] = o0;
    op[1] = o1;
}

extern "C" void kernel_launch(void* const* d_in, const int* in_sizes, int n_in,
                              void* d_out, int out_size)
{
    int idx_slot = 0, feat_slot = 1;
    if (n_in >= 2 && in_sizes[0] > in_sizes[1]) { idx_slot = 1; feat_slot = 0; }

    const int*   neigh_idx = (const int*)d_in[idx_slot];     // [B, K] int32
    const float* features  = (const float*)d_in[feat_slot];  // [U, D] fp32
    float*       out       = (float*)d_out;                  // [B, D] fp32

    const int B  = in_sizes[idx_slot] / K_NEIGH;
    const int n8 = in_sizes[feat_slot] / 8;                  // 639,904

    convert_kernel<<<CONV_BLOCKS, NTHREADS>>>(features, n8);

    dim3 block(NTHREADS);
    dim3 grid((B + WARPS_PER_BLOCK - 1) / WARPS_PER_BLOCK);
    gather_kernel<<<grid, block>>>(neigh_idx, out, B);
}